// round 4
// baseline (speedup 1.0000x reference)
#include <cuda_runtime.h>
#include <cuda_bf16.h>

// Problem constants
#define N_NODES   100000
#define N_EDGES   1600000
#define E_TOT     (N_EDGES + N_NODES)   // with self-loops
#define N_FEAT    128
#define N_CLASSES 10
#define N_GRAPHS  256

#define SCAN_B    512
#define NB_SCAN   ((N_NODES + SCAN_B - 1) / SCAN_B)   // 196

// ---------------- device scratch ----------------
__device__ __align__(16) float d_h1 [N_NODES * 64];
__device__ __align__(16) float d_als1[N_NODES * 8];
__device__ __align__(16) float d_ald1[N_NODES * 8];
__device__ __align__(16) float d_out1[N_NODES * 64];
__device__ __align__(16) float d_h2 [N_NODES * 128];
__device__ __align__(16) float d_als2[N_NODES];
__device__ __align__(16) float d_ald2[N_NODES];
__device__ __align__(16) float d_out2[N_NODES * 128];
__device__ __align__(16) float d_pool[N_GRAPHS * 128];

// CSR scratch
__device__ int d_deg   [N_NODES];
__device__ int d_incl  [N_NODES];
__device__ int d_bsum  [256];
__device__ int d_bofs  [256];
__device__ int d_rowptr[N_NODES + 1];
__device__ int d_wofs  [N_NODES];
__device__ int d_esrc  [E_TOT];

__device__ __forceinline__ float lrelu(float v) { return v > 0.f ? v : 0.2f * v; }

// ================= zero + CSR build =================
__global__ void k_zero() {
    int i = blockIdx.x * SCAN_B + threadIdx.x;
    if (i < N_NODES) d_deg[i] = 0;
    if (i < N_GRAPHS * 128) d_pool[i] = 0.f;
}

__global__ void k_hist(const int* __restrict__ ei) {
    int e = blockIdx.x * 256 + threadIdx.x;
    if (e >= E_TOT) return;
    int dst = (e < N_EDGES) ? ei[N_EDGES + e] : (e - N_EDGES);
    atomicAdd(&d_deg[dst], 1);
}

__global__ __launch_bounds__(SCAN_B) void k_scan1() {
    __shared__ int s[SCAN_B];
    int i = blockIdx.x * SCAN_B + threadIdx.x;
    int v = (i < N_NODES) ? d_deg[i] : 0;
    s[threadIdx.x] = v;
    __syncthreads();
#pragma unroll
    for (int off = 1; off < SCAN_B; off <<= 1) {
        int t = (threadIdx.x >= off) ? s[threadIdx.x - off] : 0;
        __syncthreads();
        s[threadIdx.x] += t;
        __syncthreads();
    }
    if (i < N_NODES) d_incl[i] = s[threadIdx.x];
    if (threadIdx.x == SCAN_B - 1) d_bsum[blockIdx.x] = s[SCAN_B - 1];
}

__global__ __launch_bounds__(256) void k_scan2() {
    __shared__ int s[256];
    int t = threadIdx.x;
    int v = (t < NB_SCAN) ? d_bsum[t] : 0;
    s[t] = v;
    __syncthreads();
#pragma unroll
    for (int off = 1; off < 256; off <<= 1) {
        int u = (t >= off) ? s[t - off] : 0;
        __syncthreads();
        s[t] += u;
        __syncthreads();
    }
    if (t < NB_SCAN) d_bofs[t] = s[t] - v;   // exclusive
}

__global__ __launch_bounds__(SCAN_B) void k_scan3() {
    int i = blockIdx.x * SCAN_B + threadIdx.x;
    if (i < N_NODES) {
        int v = d_incl[i] + d_bofs[blockIdx.x];
        d_rowptr[i + 1] = v;
        if (i + 1 < N_NODES) d_wofs[i + 1] = v;
    }
    if (i == 0) { d_rowptr[0] = 0; d_wofs[0] = 0; }
}

__global__ void k_scatter(const int* __restrict__ ei) {
    int e = blockIdx.x * 256 + threadIdx.x;
    if (e >= E_TOT) return;
    int src, dst;
    if (e < N_EDGES) { src = ei[e]; dst = ei[N_EDGES + e]; }
    else             { src = dst = e - N_EDGES; }
    int pos = atomicAdd(&d_wofs[dst], 1);
    d_esrc[pos] = src;
}

// ================= K1: h1 = x @ W1 (100000x128 @ 128x64), exact grid =================
#define NPB1 32
__global__ __launch_bounds__(256) void k1_gemm(const float* __restrict__ x,
                                               const float* __restrict__ W1) {
    __shared__ float Ws[128 * 64];
    __shared__ float xs[NPB1 * 128];
    int t  = threadIdx.x;
    int nb = blockIdx.x * NPB1;
    {
        const float4* W4 = (const float4*)W1;
        float4* Wd = (float4*)Ws;
        for (int i = t; i < 128 * 64 / 4; i += 256) Wd[i] = W4[i];
        const float4* x4 = (const float4*)(x + nb * 128);
        float4* xd = (float4*)xs;
        for (int i = t; i < NPB1 * 128 / 4; i += 256) xd[i] = x4[i];
    }
    __syncthreads();
    int o   = t & 63;
    int nl0 = t >> 6;   // 0..3
    float acc[8];
#pragma unroll
    for (int r = 0; r < 8; r++) acc[r] = 0.f;
    const float4* xs4 = (const float4*)xs;
#pragma unroll 4
    for (int k4 = 0; k4 < 32; k4++) {
        float w0 = Ws[(k4 * 4 + 0) * 64 + o];
        float w1 = Ws[(k4 * 4 + 1) * 64 + o];
        float w2 = Ws[(k4 * 4 + 2) * 64 + o];
        float w3 = Ws[(k4 * 4 + 3) * 64 + o];
#pragma unroll
        for (int r = 0; r < 8; r++) {
            float4 xv = xs4[(nl0 + r * 4) * 32 + k4];
            acc[r] += xv.x * w0 + xv.y * w1 + xv.z * w2 + xv.w * w3;
        }
    }
#pragma unroll
    for (int r = 0; r < 8; r++)
        d_h1[(nb + nl0 + r * 4) * 64 + o] = acc[r];
}

// ================= K1b: layer1 attention logits =================
__global__ void k1b_al(const float* __restrict__ a_src1,
                       const float* __restrict__ a_dst1) {
    int gid = blockIdx.x * blockDim.x + threadIdx.x;
    if (gid >= N_NODES * 8) return;
    int n = gid >> 3, h = gid & 7;
    float s = 0.f, d = 0.f;
#pragma unroll
    for (int c = 0; c < 8; c++) {
        float v = d_h1[n * 64 + h * 8 + c];
        s += v * a_src1[h * 8 + c];
        d += v * a_dst1[h * 8 + c];
    }
    d_als1[gid] = s;
    d_ald1[gid] = d;
}

// ================= L1 aggregation: warp per dst node =================
__global__ __launch_bounds__(256) void l1_agg(const float* __restrict__ b1) {
    int gw   = (blockIdx.x * 256 + threadIdx.x) >> 5;
    int lane = threadIdx.x & 31;
    if (gw >= N_NODES) return;
    int dst = gw;
    int beg = d_rowptr[dst], end = d_rowptr[dst + 1];
    int h8 = lane & 7;
    float ald_h = d_ald1[dst * 8 + h8];

    // pass 1: denominator (4 edges in flight; lanes 0-7 per edge cover heads)
    float sum = 0.f;
    for (int i = beg + (lane >> 3); i < end; i += 4) {
        int src = d_esrc[i];
        sum += __expf(lrelu(d_als1[src * 8 + h8] + ald_h));
    }
    sum += __shfl_xor_sync(0xffffffffu, sum, 8);
    sum += __shfl_xor_sync(0xffffffffu, sum, 16);
    float inv = 1.f / (sum + 1e-16f);

    // pass 2: aggregate. lane owns cols [2*lane, 2*lane+1], head = lane>>2
    int myhead = lane >> 2;
    float inv_my = __shfl_sync(0xffffffffu, inv, myhead);
    float acc0 = 0.f, acc1 = 0.f;
#pragma unroll 4
    for (int i = beg; i < end; i++) {
        int src = d_esrc[i];
        float e_h = __expf(lrelu(d_als1[src * 8 + h8] + ald_h));
        float alpha = __shfl_sync(0xffffffffu, e_h, myhead) * inv_my;
        float2 hv = *(const float2*)(d_h1 + src * 64 + lane * 2);
        acc0 += hv.x * alpha;
        acc1 += hv.y * alpha;
    }
    float r0 = acc0 + b1[lane * 2];
    float r1 = acc1 + b1[lane * 2 + 1];
    r0 = r0 > 0.f ? r0 : 0.f;
    r1 = r1 > 0.f ? r1 : 0.f;
    *(float2*)(d_out1 + dst * 64 + lane * 2) = make_float2(r0, r1);
}

// ================= K5: h2 = out1 @ W2 (100000x64 @ 64x128), exact grid =================
#define NPB2 32
__global__ __launch_bounds__(256) void k5_gemm(const float* __restrict__ W2) {
    __shared__ float Ws[64 * 128];
    __shared__ float xs[NPB2 * 64];
    int t  = threadIdx.x;
    int nb = blockIdx.x * NPB2;
    {
        const float4* W4 = (const float4*)W2;
        float4* Wd = (float4*)Ws;
        for (int i = t; i < 64 * 128 / 4; i += 256) Wd[i] = W4[i];
        const float4* x4 = (const float4*)(d_out1 + nb * 64);
        float4* xd = (float4*)xs;
        for (int i = t; i < NPB2 * 64 / 4; i += 256) xd[i] = x4[i];
    }
    __syncthreads();
    int o   = t & 127;
    int nl0 = t >> 7;   // 0..1
    float acc[16];
#pragma unroll
    for (int r = 0; r < 16; r++) acc[r] = 0.f;
    const float4* xs4 = (const float4*)xs;
#pragma unroll 2
    for (int k4 = 0; k4 < 16; k4++) {
        float w0 = Ws[(k4 * 4 + 0) * 128 + o];
        float w1 = Ws[(k4 * 4 + 1) * 128 + o];
        float w2 = Ws[(k4 * 4 + 2) * 128 + o];
        float w3 = Ws[(k4 * 4 + 3) * 128 + o];
#pragma unroll
        for (int r = 0; r < 16; r++) {
            float4 xv = xs4[(nl0 + r * 2) * 16 + k4];
            acc[r] += xv.x * w0 + xv.y * w1 + xv.z * w2 + xv.w * w3;
        }
    }
#pragma unroll
    for (int r = 0; r < 16; r++)
        d_h2[(nb + nl0 + r * 2) * 128 + o] = acc[r];
}

// ================= K5b: layer2 attention logits =================
__global__ void k5b_al(const float* __restrict__ a_src2,
                       const float* __restrict__ a_dst2) {
    int n = blockIdx.x * blockDim.x + threadIdx.x;
    if (n >= N_NODES) return;
    float s = 0.f, d = 0.f;
    const float4* hr  = (const float4*)(d_h2 + n * 128);
    const float4* asv = (const float4*)a_src2;
    const float4* adv = (const float4*)a_dst2;
#pragma unroll 8
    for (int k = 0; k < 32; k++) {
        float4 h = hr[k], a = asv[k], b = adv[k];
        s += h.x * a.x + h.y * a.y + h.z * a.z + h.w * a.w;
        d += h.x * b.x + h.y * b.y + h.z * b.z + h.w * b.w;
    }
    d_als2[n] = s;
    d_ald2[n] = d;
}

// ================= L2 aggregation: warp per dst node (1 head, 128 ch) =================
__global__ __launch_bounds__(256) void l2_agg() {
    int gw   = (blockIdx.x * 256 + threadIdx.x) >> 5;
    int lane = threadIdx.x & 31;
    if (gw >= N_NODES) return;
    int dst = gw;
    int beg = d_rowptr[dst], end = d_rowptr[dst + 1];
    float ald = d_ald2[dst];

    // pass 1: denominator
    float sum = 0.f;
    for (int i = beg + lane; i < end; i += 32)
        sum += __expf(lrelu(d_als2[d_esrc[i]] + ald));
#pragma unroll
    for (int o = 16; o; o >>= 1) sum += __shfl_xor_sync(0xffffffffu, sum, o);
    float inv = 1.f / (sum + 1e-16f);

    // pass 2: aggregate. lane owns cols [4*lane, 4*lane+3]
    float4 acc = make_float4(0.f, 0.f, 0.f, 0.f);
#pragma unroll 4
    for (int i = beg; i < end; i++) {
        int src = d_esrc[i];
        float alpha = __expf(lrelu(d_als2[src] + ald)) * inv;
        float4 h = *(const float4*)(d_h2 + src * 128 + lane * 4);
        acc.x += h.x * alpha;
        acc.y += h.y * alpha;
        acc.z += h.z * alpha;
        acc.w += h.w * alpha;
    }
    *(float4*)(d_out2 + dst * 128 + lane * 4) = acc;
}

// ================= pool: chunked accumulation over sorted batch =================
#define PCHUNK 512
__global__ __launch_bounds__(128) void k_pool_acc(const int* __restrict__ batch) {
    int n0 = blockIdx.x * PCHUNK;
    int n1 = min(n0 + PCHUNK, N_NODES);
    int t  = threadIdx.x;
    float acc = 0.f;
    int cur = batch[n0];
    for (int n = n0; n < n1; n++) {
        int g = batch[n];
        if (g != cur) {
            atomicAdd(&d_pool[cur * 128 + t], acc);
            acc = 0.f;
            cur = g;
        }
        acc += d_out2[n * 128 + t];
    }
    atomicAdd(&d_pool[cur * 128 + t], acc);
}

__global__ __launch_bounds__(128) void k_pool_fin(const int* __restrict__ batch,
                                                  const float* __restrict__ b2,
                                                  const float* __restrict__ fc_w,
                                                  const float* __restrict__ fc_b,
                                                  float* __restrict__ out) {
    int g = blockIdx.x;
    int t = threadIdx.x;
    int lo, hi;
    {
        int a = 0, b = N_NODES;
        while (a < b) { int m = (a + b) >> 1; if (batch[m] < g) a = m + 1; else b = m; }
        lo = a;
        a = lo; b = N_NODES;
        while (a < b) { int m = (a + b) >> 1; if (batch[m] < g + 1) a = m + 1; else b = m; }
        hi = a;
    }
    int cnt = hi - lo;
    float inv = 1.f / (float)max(cnt, 1);
    __shared__ float sp[128];
    sp[t] = (d_pool[g * 128 + t] + (float)cnt * b2[t]) * inv;
    __syncthreads();
    __shared__ float sl[N_CLASSES];
    if (t < N_CLASSES) {
        float v = fc_b[t];
        for (int k = 0; k < 128; k++) v += sp[k] * fc_w[k * N_CLASSES + t];
        sl[t] = v;
    }
    __syncthreads();
    __shared__ float s_m, s_lse;
    if (t == 0) {
        float m = sl[0];
        for (int c = 1; c < N_CLASSES; c++) m = fmaxf(m, sl[c]);
        float se = 0.f;
        for (int c = 0; c < N_CLASSES; c++) se += expf(sl[c] - m);
        s_m = m;
        s_lse = logf(se);
    }
    __syncthreads();
    if (t < N_CLASSES) out[g * N_CLASSES + t] = sl[t] - s_m - s_lse;
}

// ================= launch =================
extern "C" void kernel_launch(void* const* d_in, const int* in_sizes, int n_in,
                              void* d_out, int out_size) {
    const float* x      = (const float*)d_in[0];
    const int*   ei     = (const int*)d_in[1];
    const int*   batch  = (const int*)d_in[2];
    const float* W1     = (const float*)d_in[3];
    const float* a_src1 = (const float*)d_in[4];
    const float* a_dst1 = (const float*)d_in[5];
    const float* b1     = (const float*)d_in[6];
    const float* W2     = (const float*)d_in[7];
    const float* a_src2 = (const float*)d_in[8];
    const float* a_dst2 = (const float*)d_in[9];
    const float* b2     = (const float*)d_in[10];
    const float* fc_w   = (const float*)d_in[11];
    const float* fc_b   = (const float*)d_in[12];
    float* out = (float*)d_out;

    const int EB = (E_TOT + 255) / 256;
    const int WB = (N_NODES * 32 + 255) / 256;

    // CSR build
    k_zero<<<NB_SCAN, SCAN_B>>>();
    k_hist<<<EB, 256>>>(ei);
    k_scan1<<<NB_SCAN, SCAN_B>>>();
    k_scan2<<<1, 256>>>();
    k_scan3<<<NB_SCAN, SCAN_B>>>();
    k_scatter<<<EB, 256>>>(ei);

    // layer 1
    k1_gemm<<<N_NODES / NPB1, 256>>>(x, W1);
    k1b_al<<<(N_NODES * 8 + 255) / 256, 256>>>(a_src1, a_dst1);
    l1_agg<<<WB, 256>>>(b1);

    // layer 2
    k5_gemm<<<N_NODES / NPB2, 256>>>(W2);
    k5b_al<<<(N_NODES + 255) / 256, 256>>>(a_src2, a_dst2);
    l2_agg<<<WB, 256>>>();

    // readout
    k_pool_acc<<<(N_NODES + PCHUNK - 1) / PCHUNK, 128>>>(batch);
    k_pool_fin<<<N_GRAPHS, 128>>>(batch, b2, fc_w, fc_b, out);
}

// round 5
// speedup vs baseline: 1.3781x; 1.3781x over previous
#include <cuda_runtime.h>
#include <cuda_bf16.h>

// Problem constants
#define N_NODES   100000
#define N_EDGES   1600000
#define E_TOT     (N_EDGES + N_NODES)   // with self-loops
#define N_FEAT    128
#define N_CLASSES 10
#define N_GRAPHS  256

#define SCAN_B    512
#define NB_SCAN   ((N_NODES + SCAN_B - 1) / SCAN_B)   // 196

// ---------------- device scratch ----------------
__device__ __align__(16) float d_h1 [N_NODES * 64];
__device__ __align__(16) float d_als1[N_NODES * 8];
__device__ __align__(16) float d_ald1[N_NODES * 8];
__device__ __align__(16) float d_out1[N_NODES * 64];
__device__ __align__(16) float d_h2 [N_NODES * 128];
__device__ __align__(16) float d_als2[N_NODES];
__device__ __align__(16) float d_ald2[N_NODES];
__device__ __align__(16) float d_out2[N_NODES * 128];

// CSR scratch
__device__ int d_deg   [N_NODES];
__device__ int d_incl  [N_NODES];
__device__ int d_bsum  [256];
__device__ int d_bofs  [256];
__device__ int d_rowptr[N_NODES + 1];
__device__ int d_wofs  [N_NODES];
__device__ int d_esrc  [E_TOT];

__device__ __forceinline__ float lrelu(float v) { return v > 0.f ? v : 0.2f * v; }

// ================= CSR build =================
__global__ void k_zero_deg() {
    int i = blockIdx.x * SCAN_B + threadIdx.x;
    if (i < N_NODES) d_deg[i] = 0;
}

__global__ void k_hist(const int* __restrict__ ei) {
    int e = blockIdx.x * 256 + threadIdx.x;
    if (e >= E_TOT) return;
    int dst = (e < N_EDGES) ? ei[N_EDGES + e] : (e - N_EDGES);
    atomicAdd(&d_deg[dst], 1);
}

__global__ __launch_bounds__(SCAN_B) void k_scan1() {
    __shared__ int s[SCAN_B];
    int i = blockIdx.x * SCAN_B + threadIdx.x;
    int v = (i < N_NODES) ? d_deg[i] : 0;
    s[threadIdx.x] = v;
    __syncthreads();
#pragma unroll
    for (int off = 1; off < SCAN_B; off <<= 1) {
        int t = (threadIdx.x >= off) ? s[threadIdx.x - off] : 0;
        __syncthreads();
        s[threadIdx.x] += t;
        __syncthreads();
    }
    if (i < N_NODES) d_incl[i] = s[threadIdx.x];
    if (threadIdx.x == SCAN_B - 1) d_bsum[blockIdx.x] = s[SCAN_B - 1];
}

__global__ __launch_bounds__(256) void k_scan2() {
    __shared__ int s[256];
    int t = threadIdx.x;
    int v = (t < NB_SCAN) ? d_bsum[t] : 0;
    s[t] = v;
    __syncthreads();
#pragma unroll
    for (int off = 1; off < 256; off <<= 1) {
        int u = (t >= off) ? s[t - off] : 0;
        __syncthreads();
        s[t] += u;
        __syncthreads();
    }
    if (t < NB_SCAN) d_bofs[t] = s[t] - v;   // exclusive
}

__global__ __launch_bounds__(SCAN_B) void k_scan3() {
    int i = blockIdx.x * SCAN_B + threadIdx.x;
    if (i < N_NODES) {
        int v = d_incl[i] + d_bofs[blockIdx.x];
        d_rowptr[i + 1] = v;
        if (i + 1 < N_NODES) d_wofs[i + 1] = v;
    }
    if (i == 0) { d_rowptr[0] = 0; d_wofs[0] = 0; }
}

__global__ void k_scatter(const int* __restrict__ ei) {
    int e = blockIdx.x * 256 + threadIdx.x;
    if (e >= E_TOT) return;
    int src, dst;
    if (e < N_EDGES) { src = ei[e]; dst = ei[N_EDGES + e]; }
    else             { src = dst = e - N_EDGES; }
    int pos = atomicAdd(&d_wofs[dst], 1);
    d_esrc[pos] = src;
}

// ================= K1: h1 = x @ W1 (100000x128 @ 128x64) =================
#define NPB1 32
__global__ __launch_bounds__(256) void k1_gemm(const float* __restrict__ x,
                                               const float* __restrict__ W1) {
    __shared__ float Ws[128 * 64];
    __shared__ float xs[NPB1 * 128];
    int t  = threadIdx.x;
    int nb = blockIdx.x * NPB1;
    for (int i = t; i < 128 * 64; i += 256) Ws[i] = W1[i];
    for (int i = t; i < NPB1 * 128; i += 256) {
        int nl = i >> 7, k = i & 127;
        int n = nb + nl;
        xs[i] = (n < N_NODES) ? x[n * 128 + k] : 0.f;
    }
    __syncthreads();
    int o = t & 63;
    int nl0 = t >> 6;
    float acc[8];
#pragma unroll
    for (int r = 0; r < 8; r++) acc[r] = 0.f;
    for (int k = 0; k < 128; k++) {
        float w = Ws[k * 64 + o];
#pragma unroll
        for (int r = 0; r < 8; r++)
            acc[r] += xs[(nl0 + r * 4) * 128 + k] * w;
    }
#pragma unroll
    for (int r = 0; r < 8; r++) {
        int n = nb + nl0 + r * 4;
        if (n < N_NODES) d_h1[n * 64 + o] = acc[r];
    }
}

// ================= K1b: layer1 attention logits =================
__global__ void k1b_al(const float* __restrict__ a_src1,
                       const float* __restrict__ a_dst1) {
    int gid = blockIdx.x * blockDim.x + threadIdx.x;
    if (gid >= N_NODES * 8) return;
    int n = gid >> 3, h = gid & 7;
    float s = 0.f, d = 0.f;
#pragma unroll
    for (int c = 0; c < 8; c++) {
        float v = d_h1[n * 64 + h * 8 + c];
        s += v * a_src1[h * 8 + c];
        d += v * a_dst1[h * 8 + c];
    }
    d_als1[gid] = s;
    d_ald1[gid] = d;
}

// ================= L1 aggregation: warp per dst node =================
__global__ __launch_bounds__(256) void l1_agg(const float* __restrict__ b1) {
    int gw   = (blockIdx.x * 256 + threadIdx.x) >> 5;
    int lane = threadIdx.x & 31;
    if (gw >= N_NODES) return;
    int dst = gw;
    int beg = d_rowptr[dst], end = d_rowptr[dst + 1];
    int h8 = lane & 7;
    float ald_h = d_ald1[dst * 8 + h8];

    // pass 1: denominator (4 edges in flight; lanes 0-7 per edge cover heads)
    float sum = 0.f;
    for (int i = beg + (lane >> 3); i < end; i += 4) {
        int src = d_esrc[i];
        sum += __expf(lrelu(d_als1[src * 8 + h8] + ald_h));
    }
    sum += __shfl_xor_sync(0xffffffffu, sum, 8);
    sum += __shfl_xor_sync(0xffffffffu, sum, 16);
    float inv = 1.f / (sum + 1e-16f);

    // pass 2: aggregate. lane owns cols [2*lane, 2*lane+1], head = lane>>2
    int myhead = lane >> 2;
    float inv_my = __shfl_sync(0xffffffffu, inv, myhead);
    float acc0 = 0.f, acc1 = 0.f;
#pragma unroll 2
    for (int i = beg; i < end; i++) {
        int src = d_esrc[i];
        float e_h = __expf(lrelu(d_als1[src * 8 + h8] + ald_h));
        float alpha = __shfl_sync(0xffffffffu, e_h, myhead) * inv_my;
        float2 hv = *(const float2*)(d_h1 + src * 64 + lane * 2);
        acc0 += hv.x * alpha;
        acc1 += hv.y * alpha;
    }
    float r0 = acc0 + b1[lane * 2];
    float r1 = acc1 + b1[lane * 2 + 1];
    r0 = r0 > 0.f ? r0 : 0.f;
    r1 = r1 > 0.f ? r1 : 0.f;
    *(float2*)(d_out1 + dst * 64 + lane * 2) = make_float2(r0, r1);
}

// ================= K5: h2 = out1 @ W2 (100000x64 @ 64x128) =================
#define NPB2 32
__global__ __launch_bounds__(256) void k5_gemm(const float* __restrict__ W2) {
    __shared__ float Ws[64 * 128];
    __shared__ float xs[NPB2 * 64];
    int t  = threadIdx.x;
    int nb = blockIdx.x * NPB2;
    for (int i = t; i < 64 * 128; i += 256) Ws[i] = W2[i];
    for (int i = t; i < NPB2 * 64; i += 256) {
        int nl = i >> 6, k = i & 63;
        int n = nb + nl;
        xs[i] = (n < N_NODES) ? d_out1[n * 64 + k] : 0.f;
    }
    __syncthreads();
    int o = t & 127;
    int nl0 = t >> 7;
    float acc[16];
#pragma unroll
    for (int r = 0; r < 16; r++) acc[r] = 0.f;
    for (int k = 0; k < 64; k++) {
        float w = Ws[k * 128 + o];
#pragma unroll
        for (int r = 0; r < 16; r++)
            acc[r] += xs[(nl0 + r * 2) * 64 + k] * w;
    }
#pragma unroll
    for (int r = 0; r < 16; r++) {
        int n = nb + nl0 + r * 2;
        if (n < N_NODES) d_h2[n * 128 + o] = acc[r];
    }
}

// ================= K5b: layer2 attention logits =================
__global__ void k5b_al(const float* __restrict__ a_src2,
                       const float* __restrict__ a_dst2) {
    int n = blockIdx.x * blockDim.x + threadIdx.x;
    if (n >= N_NODES) return;
    float s = 0.f, d = 0.f;
    const float4* hr  = (const float4*)(d_h2 + n * 128);
    const float4* asv = (const float4*)a_src2;
    const float4* adv = (const float4*)a_dst2;
#pragma unroll 8
    for (int k = 0; k < 32; k++) {
        float4 h = hr[k], a = asv[k], b = adv[k];
        s += h.x * a.x + h.y * a.y + h.z * a.z + h.w * a.w;
        d += h.x * b.x + h.y * b.y + h.z * b.z + h.w * b.w;
    }
    d_als2[n] = s;
    d_ald2[n] = d;
}

// ================= L2 aggregation: warp per dst node (1 head, 128 ch) =================
__global__ __launch_bounds__(256) void l2_agg() {
    int gw   = (blockIdx.x * 256 + threadIdx.x) >> 5;
    int lane = threadIdx.x & 31;
    if (gw >= N_NODES) return;
    int dst = gw;
    int beg = d_rowptr[dst], end = d_rowptr[dst + 1];
    float ald = d_ald2[dst];

    // pass 1: denominator, 32 edges in flight
    float sum = 0.f;
    for (int i = beg + lane; i < end; i += 32)
        sum += __expf(lrelu(d_als2[d_esrc[i]] + ald));
#pragma unroll
    for (int o = 16; o; o >>= 1) sum += __shfl_xor_sync(0xffffffffu, sum, o);
    float inv = 1.f / (sum + 1e-16f);

    // pass 2: aggregate. lane owns cols [4*lane, 4*lane+3]
    float4 acc = make_float4(0.f, 0.f, 0.f, 0.f);
#pragma unroll 2
    for (int i = beg; i < end; i++) {
        int src = d_esrc[i];
        float alpha = __expf(lrelu(d_als2[src] + ald)) * inv;
        float4 h = *(const float4*)(d_h2 + src * 128 + lane * 4);
        acc.x += h.x * alpha;
        acc.y += h.y * alpha;
        acc.z += h.z * alpha;
        acc.w += h.w * alpha;
    }
    *(float4*)(d_out2 + dst * 128 + lane * 4) = acc;
}

// ================= K8: pool + FC + log_softmax =================
__global__ __launch_bounds__(128) void k8_pool(const int* __restrict__ batch,
                                               const float* __restrict__ b2,
                                               const float* __restrict__ fc_w,
                                               const float* __restrict__ fc_b,
                                               float* __restrict__ out) {
    int g = blockIdx.x;
    int t = threadIdx.x;
    int lo, hi;
    {
        int a = 0, b = N_NODES;
        while (a < b) { int m = (a + b) >> 1; if (batch[m] < g) a = m + 1; else b = m; }
        lo = a;
        a = lo; b = N_NODES;
        while (a < b) { int m = (a + b) >> 1; if (batch[m] < g + 1) a = m + 1; else b = m; }
        hi = a;
    }
    int cnt = hi - lo;
    float acc = 0.f;
    for (int n = lo; n < hi; n++) acc += d_out2[n * 128 + t];
    float inv = 1.f / (float)max(cnt, 1);
    __shared__ float sp[128];
    sp[t] = (acc + (float)cnt * b2[t]) * inv;
    __syncthreads();
    __shared__ float sl[N_CLASSES];
    if (t < N_CLASSES) {
        float v = fc_b[t];
        for (int k = 0; k < 128; k++) v += sp[k] * fc_w[k * N_CLASSES + t];
        sl[t] = v;
    }
    __syncthreads();
    __shared__ float s_m, s_lse;
    if (t == 0) {
        float m = sl[0];
        for (int c = 1; c < N_CLASSES; c++) m = fmaxf(m, sl[c]);
        float se = 0.f;
        for (int c = 0; c < N_CLASSES; c++) se += expf(sl[c] - m);
        s_m = m;
        s_lse = logf(se);
    }
    __syncthreads();
    if (t < N_CLASSES) out[g * N_CLASSES + t] = sl[t] - s_m - s_lse;
}

// ================= launch =================
extern "C" void kernel_launch(void* const* d_in, const int* in_sizes, int n_in,
                              void* d_out, int out_size) {
    const float* x      = (const float*)d_in[0];
    const int*   ei     = (const int*)d_in[1];
    const int*   batch  = (const int*)d_in[2];
    const float* W1     = (const float*)d_in[3];
    const float* a_src1 = (const float*)d_in[4];
    const float* a_dst1 = (const float*)d_in[5];
    const float* b1     = (const float*)d_in[6];
    const float* W2     = (const float*)d_in[7];
    const float* a_src2 = (const float*)d_in[8];
    const float* a_dst2 = (const float*)d_in[9];
    const float* b2     = (const float*)d_in[10];
    const float* fc_w   = (const float*)d_in[11];
    const float* fc_b   = (const float*)d_in[12];
    float* out = (float*)d_out;

    const int EB = (E_TOT + 255) / 256;
    const int WB = (N_NODES * 32 + 255) / 256;

    // CSR build
    k_zero_deg<<<NB_SCAN, SCAN_B>>>();
    k_hist<<<EB, 256>>>(ei);
    k_scan1<<<NB_SCAN, SCAN_B>>>();
    k_scan2<<<1, 256>>>();
    k_scan3<<<NB_SCAN, SCAN_B>>>();
    k_scatter<<<EB, 256>>>(ei);

    // layer 1
    k1_gemm<<<(N_NODES + NPB1 - 1) / NPB1, 256>>>(x, W1);
    k1b_al<<<(N_NODES * 8 + 255) / 256, 256>>>(a_src1, a_dst1);
    l1_agg<<<WB, 256>>>(b1);

    // layer 2
    k5_gemm<<<(N_NODES + NPB2 - 1) / NPB2, 256>>>(W2);
    k5b_al<<<(N_NODES + 255) / 256, 256>>>(a_src2, a_dst2);
    l2_agg<<<WB, 256>>>();

    // readout
    k8_pool<<<N_GRAPHS, 128>>>(batch, b2, fc_w, fc_b, out);
}

// round 6
// speedup vs baseline: 1.5319x; 1.1116x over previous
#include <cuda_runtime.h>
#include <cuda_bf16.h>

// Problem constants
#define N_NODES   100000
#define N_EDGES   1600000
#define E_TOT     (N_EDGES + N_NODES)   // with self-loops
#define N_FEAT    128
#define N_CLASSES 10
#define N_GRAPHS  256

#define SCAN_B    512
#define NB_SCAN   ((N_NODES + SCAN_B - 1) / SCAN_B)   // 196

// ---------------- device scratch ----------------
__device__ __align__(16) float d_h1 [N_NODES * 64];
__device__ __align__(16) float d_als1[N_NODES * 8];
__device__ __align__(16) float d_ald1[N_NODES * 8];
__device__ __align__(16) float d_out1[N_NODES * 64];
__device__ __align__(16) float d_h2 [N_NODES * 128];
__device__ __align__(16) float d_als2[N_NODES];
__device__ __align__(16) float d_ald2[N_NODES];
__device__ __align__(16) float d_out2[N_NODES * 128];

// CSR scratch
__device__ int d_deg   [N_NODES];
__device__ int d_incl  [N_NODES];
__device__ int d_bsum  [256];
__device__ int d_bofs  [256];
__device__ int d_rowptr[N_NODES + 1];
__device__ int d_wofs  [N_NODES];
__device__ int d_esrc  [E_TOT];

__device__ __forceinline__ float lrelu(float v) { return v > 0.f ? v : 0.2f * v; }

// ================= CSR build =================
__global__ void k_zero_deg() {
    int i = blockIdx.x * SCAN_B + threadIdx.x;
    if (i < N_NODES) d_deg[i] = 0;
}

__global__ void k_hist(const int* __restrict__ ei) {
    int e = blockIdx.x * 256 + threadIdx.x;
    if (e >= E_TOT) return;
    int dst = (e < N_EDGES) ? ei[N_EDGES + e] : (e - N_EDGES);
    atomicAdd(&d_deg[dst], 1);
}

__global__ __launch_bounds__(SCAN_B) void k_scan1() {
    __shared__ int s[SCAN_B];
    int i = blockIdx.x * SCAN_B + threadIdx.x;
    int v = (i < N_NODES) ? d_deg[i] : 0;
    s[threadIdx.x] = v;
    __syncthreads();
#pragma unroll
    for (int off = 1; off < SCAN_B; off <<= 1) {
        int t = (threadIdx.x >= off) ? s[threadIdx.x - off] : 0;
        __syncthreads();
        s[threadIdx.x] += t;
        __syncthreads();
    }
    if (i < N_NODES) d_incl[i] = s[threadIdx.x];
    if (threadIdx.x == SCAN_B - 1) d_bsum[blockIdx.x] = s[SCAN_B - 1];
}

__global__ __launch_bounds__(256) void k_scan2() {
    __shared__ int s[256];
    int t = threadIdx.x;
    int v = (t < NB_SCAN) ? d_bsum[t] : 0;
    s[t] = v;
    __syncthreads();
#pragma unroll
    for (int off = 1; off < 256; off <<= 1) {
        int u = (t >= off) ? s[t - off] : 0;
        __syncthreads();
        s[t] += u;
        __syncthreads();
    }
    if (t < NB_SCAN) d_bofs[t] = s[t] - v;   // exclusive
}

__global__ __launch_bounds__(SCAN_B) void k_scan3() {
    int i = blockIdx.x * SCAN_B + threadIdx.x;
    if (i < N_NODES) {
        int v = d_incl[i] + d_bofs[blockIdx.x];
        d_rowptr[i + 1] = v;
        if (i + 1 < N_NODES) d_wofs[i + 1] = v;
    }
    if (i == 0) { d_rowptr[0] = 0; d_wofs[0] = 0; }
}

__global__ void k_scatter(const int* __restrict__ ei) {
    int e = blockIdx.x * 256 + threadIdx.x;
    if (e >= E_TOT) return;
    int src, dst;
    if (e < N_EDGES) { src = ei[e]; dst = ei[N_EDGES + e]; }
    else             { src = dst = e - N_EDGES; }
    int pos = atomicAdd(&d_wofs[dst], 1);
    d_esrc[pos] = src;
}

// ================= K1: h1 = x @ W1 (100000x128 @ 128x64) + fused logits =================
// exact grid: 100000/32 = 3125 blocks
#define NPB1 32
__global__ __launch_bounds__(256) void k1_gemm(const float* __restrict__ x,
                                               const float* __restrict__ W1,
                                               const float* __restrict__ a_src1,
                                               const float* __restrict__ a_dst1) {
    __shared__ float Ws[128 * 64];
    __shared__ float xs[NPB1 * 128];
    int t  = threadIdx.x;
    int nb = blockIdx.x * NPB1;
    {
        const float4* W4 = (const float4*)W1;
        float4* Wd = (float4*)Ws;
        for (int i = t; i < 128 * 64 / 4; i += 256) Wd[i] = W4[i];
        const float4* x4 = (const float4*)(x + nb * 128);
        float4* xd = (float4*)xs;
        for (int i = t; i < NPB1 * 128 / 4; i += 256) xd[i] = x4[i];
    }
    __syncthreads();
    int o   = t & 63;   // output channel (head = o>>3, ch = o&7)
    int nl0 = t >> 6;   // 0..3
    float acc[8];
#pragma unroll
    for (int r = 0; r < 8; r++) acc[r] = 0.f;
    const float4* xs4 = (const float4*)xs;
#pragma unroll 4
    for (int k4 = 0; k4 < 32; k4++) {
        float w0 = Ws[(k4 * 4 + 0) * 64 + o];
        float w1 = Ws[(k4 * 4 + 1) * 64 + o];
        float w2 = Ws[(k4 * 4 + 2) * 64 + o];
        float w3 = Ws[(k4 * 4 + 3) * 64 + o];
#pragma unroll
        for (int r = 0; r < 8; r++) {
            float4 xv = xs4[(nl0 + r * 4) * 32 + k4];
            acc[r] += xv.x * w0 + xv.y * w1 + xv.z * w2 + xv.w * w3;
        }
    }
#pragma unroll
    for (int r = 0; r < 8; r++)
        d_h1[(nb + nl0 + r * 4) * 64 + o] = acc[r];

    // fused attention logits: reduce acc[r]*a[o] over the 8-lane channel group
    float a_s = a_src1[o];
    float a_d = a_dst1[o];
#pragma unroll
    for (int r = 0; r < 8; r++) {
        float cs = acc[r] * a_s;
        float cd = acc[r] * a_d;
#pragma unroll
        for (int off = 1; off < 8; off <<= 1) {
            cs += __shfl_xor_sync(0xffffffffu, cs, off);
            cd += __shfl_xor_sync(0xffffffffu, cd, off);
        }
        if ((o & 7) == 0) {
            int n = nb + nl0 + r * 4;
            int h = o >> 3;
            d_als1[n * 8 + h] = cs;
            d_ald1[n * 8 + h] = cd;
        }
    }
}

// ================= L1 aggregation: warp per dst node =================
__global__ __launch_bounds__(256) void l1_agg(const float* __restrict__ b1) {
    int gw   = (blockIdx.x * 256 + threadIdx.x) >> 5;
    int lane = threadIdx.x & 31;
    if (gw >= N_NODES) return;
    int dst = gw;
    int beg = d_rowptr[dst], end = d_rowptr[dst + 1];
    int h8 = lane & 7;
    float ald_h = d_ald1[dst * 8 + h8];

    // pass 1: denominator (4 edges in flight; lanes 0-7 per edge cover heads)
    float sum = 0.f;
    for (int i = beg + (lane >> 3); i < end; i += 4) {
        int src = d_esrc[i];
        sum += __expf(lrelu(d_als1[src * 8 + h8] + ald_h));
    }
    sum += __shfl_xor_sync(0xffffffffu, sum, 8);
    sum += __shfl_xor_sync(0xffffffffu, sum, 16);
    float inv = 1.f / (sum + 1e-16f);

    // pass 2: aggregate. lane owns cols [2*lane, 2*lane+1], head = lane>>2
    int myhead = lane >> 2;
    float inv_my = __shfl_sync(0xffffffffu, inv, myhead);
    float acc0 = 0.f, acc1 = 0.f;
#pragma unroll 2
    for (int i = beg; i < end; i++) {
        int src = d_esrc[i];
        float e_h = __expf(lrelu(d_als1[src * 8 + h8] + ald_h));
        float alpha = __shfl_sync(0xffffffffu, e_h, myhead) * inv_my;
        float2 hv = *(const float2*)(d_h1 + src * 64 + lane * 2);
        acc0 += hv.x * alpha;
        acc1 += hv.y * alpha;
    }
    float r0 = acc0 + b1[lane * 2];
    float r1 = acc1 + b1[lane * 2 + 1];
    r0 = r0 > 0.f ? r0 : 0.f;
    r1 = r1 > 0.f ? r1 : 0.f;
    *(float2*)(d_out1 + dst * 64 + lane * 2) = make_float2(r0, r1);
}

// ================= K5: h2 = out1 @ W2 (100000x64 @ 64x128) + fused logits =================
#define NPB2 32
__global__ __launch_bounds__(256) void k5_gemm(const float* __restrict__ W2,
                                               const float* __restrict__ a_src2,
                                               const float* __restrict__ a_dst2) {
    __shared__ float Ws[64 * 128];
    __shared__ float xs[NPB2 * 64];
    __shared__ float sals[2][16][4];
    __shared__ float sald[2][16][4];
    int t  = threadIdx.x;
    int nb = blockIdx.x * NPB2;
    {
        const float4* W4 = (const float4*)W2;
        float4* Wd = (float4*)Ws;
        for (int i = t; i < 64 * 128 / 4; i += 256) Wd[i] = W4[i];
        const float4* x4 = (const float4*)(d_out1 + nb * 64);
        float4* xd = (float4*)xs;
        for (int i = t; i < NPB2 * 64 / 4; i += 256) xd[i] = x4[i];
    }
    __syncthreads();
    int o   = t & 127;  // output channel
    int nl0 = t >> 7;   // 0..1
    int w4  = (t >> 5) & 3;  // which quarter of channels this warp covers
    float acc[16];
#pragma unroll
    for (int r = 0; r < 16; r++) acc[r] = 0.f;
    const float4* xs4 = (const float4*)xs;
#pragma unroll 2
    for (int k4 = 0; k4 < 16; k4++) {
        float w0 = Ws[(k4 * 4 + 0) * 128 + o];
        float w1 = Ws[(k4 * 4 + 1) * 128 + o];
        float w2 = Ws[(k4 * 4 + 2) * 128 + o];
        float w3 = Ws[(k4 * 4 + 3) * 128 + o];
#pragma unroll
        for (int r = 0; r < 16; r++) {
            float4 xv = xs4[(nl0 + r * 2) * 16 + k4];
            acc[r] += xv.x * w0 + xv.y * w1 + xv.z * w2 + xv.w * w3;
        }
    }
#pragma unroll
    for (int r = 0; r < 16; r++)
        d_h2[(nb + nl0 + r * 2) * 128 + o] = acc[r];

    // fused logits: warp-reduce partial dot over this warp's 32 channels
    float a_s = a_src2[o];
    float a_d = a_dst2[o];
#pragma unroll
    for (int r = 0; r < 16; r++) {
        float cs = acc[r] * a_s;
        float cd = acc[r] * a_d;
#pragma unroll
        for (int off = 1; off < 32; off <<= 1) {
            cs += __shfl_xor_sync(0xffffffffu, cs, off);
            cd += __shfl_xor_sync(0xffffffffu, cd, off);
        }
        if ((t & 31) == 0) {
            sals[nl0][r][w4] = cs;
            sald[nl0][r][w4] = cd;
        }
    }
    __syncthreads();
    if (t < NPB2) {
        int nl = t & 1, r = t >> 1;
        d_als2[nb + t] = sals[nl][r][0] + sals[nl][r][1] + sals[nl][r][2] + sals[nl][r][3];
        d_ald2[nb + t] = sald[nl][r][0] + sald[nl][r][1] + sald[nl][r][2] + sald[nl][r][3];
    }
}

// ================= L2 aggregation: warp per dst node (1 head, 128 ch) =================
__global__ __launch_bounds__(256) void l2_agg() {
    int gw   = (blockIdx.x * 256 + threadIdx.x) >> 5;
    int lane = threadIdx.x & 31;
    if (gw >= N_NODES) return;
    int dst = gw;
    int beg = d_rowptr[dst], end = d_rowptr[dst + 1];
    float ald = d_ald2[dst];

    // pass 1: denominator, 32 edges in flight
    float sum = 0.f;
    for (int i = beg + lane; i < end; i += 32)
        sum += __expf(lrelu(d_als2[d_esrc[i]] + ald));
#pragma unroll
    for (int o = 16; o; o >>= 1) sum += __shfl_xor_sync(0xffffffffu, sum, o);
    float inv = 1.f / (sum + 1e-16f);

    // pass 2: aggregate. lane owns cols [4*lane, 4*lane+3]
    float4 acc = make_float4(0.f, 0.f, 0.f, 0.f);
#pragma unroll 2
    for (int i = beg; i < end; i++) {
        int src = d_esrc[i];
        float alpha = __expf(lrelu(d_als2[src] + ald)) * inv;
        float4 h = *(const float4*)(d_h2 + src * 128 + lane * 4);
        acc.x += h.x * alpha;
        acc.y += h.y * alpha;
        acc.z += h.z * alpha;
        acc.w += h.w * alpha;
    }
    *(float4*)(d_out2 + dst * 128 + lane * 4) = acc;
}

// ================= K8: pool + FC + log_softmax =================
__global__ __launch_bounds__(128) void k8_pool(const int* __restrict__ batch,
                                               const float* __restrict__ b2,
                                               const float* __restrict__ fc_w,
                                               const float* __restrict__ fc_b,
                                               float* __restrict__ out) {
    int g = blockIdx.x;
    int t = threadIdx.x;
    int lo, hi;
    {
        int a = 0, b = N_NODES;
        while (a < b) { int m = (a + b) >> 1; if (batch[m] < g) a = m + 1; else b = m; }
        lo = a;
        a = lo; b = N_NODES;
        while (a < b) { int m = (a + b) >> 1; if (batch[m] < g + 1) a = m + 1; else b = m; }
        hi = a;
    }
    int cnt = hi - lo;
    float acc = 0.f;
    for (int n = lo; n < hi; n++) acc += d_out2[n * 128 + t];
    float inv = 1.f / (float)max(cnt, 1);
    __shared__ float sp[128];
    sp[t] = (acc + (float)cnt * b2[t]) * inv;
    __syncthreads();
    __shared__ float sl[N_CLASSES];
    if (t < N_CLASSES) {
        float v = fc_b[t];
        for (int k = 0; k < 128; k++) v += sp[k] * fc_w[k * N_CLASSES + t];
        sl[t] = v;
    }
    __syncthreads();
    __shared__ float s_m, s_lse;
    if (t == 0) {
        float m = sl[0];
        for (int c = 1; c < N_CLASSES; c++) m = fmaxf(m, sl[c]);
        float se = 0.f;
        for (int c = 0; c < N_CLASSES; c++) se += expf(sl[c] - m);
        s_m = m;
        s_lse = logf(se);
    }
    __syncthreads();
    if (t < N_CLASSES) out[g * N_CLASSES + t] = sl[t] - s_m - s_lse;
}

// ================= launch =================
extern "C" void kernel_launch(void* const* d_in, const int* in_sizes, int n_in,
                              void* d_out, int out_size) {
    const float* x      = (const float*)d_in[0];
    const int*   ei     = (const int*)d_in[1];
    const int*   batch  = (const int*)d_in[2];
    const float* W1     = (const float*)d_in[3];
    const float* a_src1 = (const float*)d_in[4];
    const float* a_dst1 = (const float*)d_in[5];
    const float* b1     = (const float*)d_in[6];
    const float* W2     = (const float*)d_in[7];
    const float* a_src2 = (const float*)d_in[8];
    const float* a_dst2 = (const float*)d_in[9];
    const float* b2     = (const float*)d_in[10];
    const float* fc_w   = (const float*)d_in[11];
    const float* fc_b   = (const float*)d_in[12];
    float* out = (float*)d_out;

    const int EB = (E_TOT + 255) / 256;
    const int WB = (N_NODES * 32 + 255) / 256;

    // CSR build
    k_zero_deg<<<NB_SCAN, SCAN_B>>>();
    k_hist<<<EB, 256>>>(ei);
    k_scan1<<<NB_SCAN, SCAN_B>>>();
    k_scan2<<<1, 256>>>();
    k_scan3<<<NB_SCAN, SCAN_B>>>();
    k_scatter<<<EB, 256>>>(ei);

    // layer 1
    k1_gemm<<<N_NODES / NPB1, 256>>>(x, W1, a_src1, a_dst1);
    l1_agg<<<WB, 256>>>(b1);

    // layer 2
    k5_gemm<<<N_NODES / NPB2, 256>>>(W2, a_src2, a_dst2);
    l2_agg<<<WB, 256>>>();

    // readout
    k8_pool<<<N_GRAPHS, 128>>>(batch, b2, fc_w, fc_b, out);
}

// round 7
// speedup vs baseline: 1.5734x; 1.0270x over previous
#include <cuda_runtime.h>
#include <cuda_fp16.h>

// Problem constants
#define N_NODES   100000
#define N_EDGES   1600000
#define E_TOT     (N_EDGES + N_NODES)   // with self-loops
#define N_FEAT    128
#define N_CLASSES 10
#define N_GRAPHS  256

#define SCAN_B    512
#define NB_SCAN   ((N_NODES + SCAN_B - 1) / SCAN_B)   // 196

// ---------------- device scratch ----------------
__device__ __align__(16) __half d_h1h[N_NODES * 64];    // layer1 features (gather-only)
__device__ __align__(16) float  d_als1[N_NODES * 8];
__device__ __align__(16) float  d_ald1[N_NODES * 8];
__device__ __align__(16) float  d_out1[N_NODES * 64];
__device__ __align__(16) __half d_h2h[N_NODES * 128];   // layer2 features (gather-only)
__device__ __align__(16) float  d_als2[N_NODES];
__device__ __align__(16) float  d_ald2[N_NODES];
__device__ __align__(16) float  d_out2[N_NODES * 128];

// CSR scratch
__device__ int d_deg   [N_NODES];
__device__ int d_incl  [N_NODES];
__device__ int d_bsum  [256];
__device__ int d_bofs  [256];
__device__ int d_rowptr[N_NODES + 1];
__device__ int d_wofs  [N_NODES];
__device__ int d_esrc  [E_TOT];

__device__ __forceinline__ float lrelu(float v) { return v > 0.f ? v : 0.2f * v; }

// ================= CSR build =================
__global__ void k_zero_deg() {
    int i = blockIdx.x * SCAN_B + threadIdx.x;
    if (i < N_NODES) d_deg[i] = 0;
}

__global__ void k_hist(const int* __restrict__ ei) {
    int e = blockIdx.x * 256 + threadIdx.x;
    if (e >= E_TOT) return;
    int dst = (e < N_EDGES) ? ei[N_EDGES + e] : (e - N_EDGES);
    atomicAdd(&d_deg[dst], 1);
}

__global__ __launch_bounds__(SCAN_B) void k_scan1() {
    __shared__ int s[SCAN_B];
    int i = blockIdx.x * SCAN_B + threadIdx.x;
    int v = (i < N_NODES) ? d_deg[i] : 0;
    s[threadIdx.x] = v;
    __syncthreads();
#pragma unroll
    for (int off = 1; off < SCAN_B; off <<= 1) {
        int t = (threadIdx.x >= off) ? s[threadIdx.x - off] : 0;
        __syncthreads();
        s[threadIdx.x] += t;
        __syncthreads();
    }
    if (i < N_NODES) d_incl[i] = s[threadIdx.x];
    if (threadIdx.x == SCAN_B - 1) d_bsum[blockIdx.x] = s[SCAN_B - 1];
}

__global__ __launch_bounds__(256) void k_scan2() {
    __shared__ int s[256];
    int t = threadIdx.x;
    int v = (t < NB_SCAN) ? d_bsum[t] : 0;
    s[t] = v;
    __syncthreads();
#pragma unroll
    for (int off = 1; off < 256; off <<= 1) {
        int u = (t >= off) ? s[t - off] : 0;
        __syncthreads();
        s[t] += u;
        __syncthreads();
    }
    if (t < NB_SCAN) d_bofs[t] = s[t] - v;   // exclusive
}

__global__ __launch_bounds__(SCAN_B) void k_scan3() {
    int i = blockIdx.x * SCAN_B + threadIdx.x;
    if (i < N_NODES) {
        int v = d_incl[i] + d_bofs[blockIdx.x];
        d_rowptr[i + 1] = v;
        if (i + 1 < N_NODES) d_wofs[i + 1] = v;
    }
    if (i == 0) { d_rowptr[0] = 0; d_wofs[0] = 0; }
}

__global__ void k_scatter(const int* __restrict__ ei) {
    int e = blockIdx.x * 256 + threadIdx.x;
    if (e >= E_TOT) return;
    int src, dst;
    if (e < N_EDGES) { src = ei[e]; dst = ei[N_EDGES + e]; }
    else             { src = dst = e - N_EDGES; }
    int pos = atomicAdd(&d_wofs[dst], 1);
    d_esrc[pos] = src;
}

// ================= K1: h1 = x @ W1 (100000x128 @ 128x64) + fused logits =================
#define NPB1 32
__global__ __launch_bounds__(256) void k1_gemm(const float* __restrict__ x,
                                               const float* __restrict__ W1,
                                               const float* __restrict__ a_src1,
                                               const float* __restrict__ a_dst1) {
    __shared__ float Ws[128 * 64];
    __shared__ float xs[NPB1 * 128];
    int t  = threadIdx.x;
    int nb = blockIdx.x * NPB1;
    {
        const float4* W4 = (const float4*)W1;
        float4* Wd = (float4*)Ws;
        for (int i = t; i < 128 * 64 / 4; i += 256) Wd[i] = W4[i];
        const float4* x4 = (const float4*)(x + nb * 128);
        float4* xd = (float4*)xs;
        for (int i = t; i < NPB1 * 128 / 4; i += 256) xd[i] = x4[i];
    }
    __syncthreads();
    int o   = t & 63;   // output channel (head = o>>3, ch = o&7)
    int nl0 = t >> 6;   // 0..3
    float acc[8];
#pragma unroll
    for (int r = 0; r < 8; r++) acc[r] = 0.f;
    const float4* xs4 = (const float4*)xs;
#pragma unroll 4
    for (int k4 = 0; k4 < 32; k4++) {
        float w0 = Ws[(k4 * 4 + 0) * 64 + o];
        float w1 = Ws[(k4 * 4 + 1) * 64 + o];
        float w2 = Ws[(k4 * 4 + 2) * 64 + o];
        float w3 = Ws[(k4 * 4 + 3) * 64 + o];
#pragma unroll
        for (int r = 0; r < 8; r++) {
            float4 xv = xs4[(nl0 + r * 4) * 32 + k4];
            acc[r] += xv.x * w0 + xv.y * w1 + xv.z * w2 + xv.w * w3;
        }
    }
#pragma unroll
    for (int r = 0; r < 8; r++)
        d_h1h[(nb + nl0 + r * 4) * 64 + o] = __float2half_rn(acc[r]);

    // fused attention logits: reduce acc[r]*a[o] over the 8-lane channel group
    float a_s = a_src1[o];
    float a_d = a_dst1[o];
#pragma unroll
    for (int r = 0; r < 8; r++) {
        float cs = acc[r] * a_s;
        float cd = acc[r] * a_d;
#pragma unroll
        for (int off = 1; off < 8; off <<= 1) {
            cs += __shfl_xor_sync(0xffffffffu, cs, off);
            cd += __shfl_xor_sync(0xffffffffu, cd, off);
        }
        if ((o & 7) == 0) {
            int n = nb + nl0 + r * 4;
            int h = o >> 3;
            d_als1[n * 8 + h] = cs;
            d_ald1[n * 8 + h] = cd;
        }
    }
}

// ================= L1 aggregation: warp per dst node, single pass =================
__global__ __launch_bounds__(256) void l1_agg(const float* __restrict__ b1) {
    int gw   = (blockIdx.x * 256 + threadIdx.x) >> 5;
    int lane = threadIdx.x & 31;
    if (gw >= N_NODES) return;
    int dst = gw;
    int beg = d_rowptr[dst], end = d_rowptr[dst + 1];
    int h8 = lane & 7;                    // head this lane evaluates exp for
    int myhead = lane >> 2;               // head whose channels this lane owns
    float ald_h = d_ald1[dst * 8 + h8];

    float sum = 0.f;                      // denominator for head h8
    float acc0 = 0.f, acc1 = 0.f;         // channels 2*lane, 2*lane+1
#pragma unroll 2
    for (int i = beg; i < end; i++) {
        int src = d_esrc[i];
        float e_h = __expf(lrelu(d_als1[src * 8 + h8] + ald_h));
        sum += e_h;
        float alpha = __shfl_sync(0xffffffffu, e_h, myhead);
        __half2 hv = *(const __half2*)(d_h1h + src * 64 + lane * 2);
        float2 hf = __half22float2(hv);
        acc0 += hf.x * alpha;
        acc1 += hf.y * alpha;
    }
    float inv = 1.f / (__shfl_sync(0xffffffffu, sum, myhead) + 1e-16f);
    float r0 = acc0 * inv + b1[lane * 2];
    float r1 = acc1 * inv + b1[lane * 2 + 1];
    r0 = r0 > 0.f ? r0 : 0.f;
    r1 = r1 > 0.f ? r1 : 0.f;
    *(float2*)(d_out1 + dst * 64 + lane * 2) = make_float2(r0, r1);
}

// ================= K5: h2 = out1 @ W2 (100000x64 @ 64x128) + fused logits =================
#define NPB2 32
__global__ __launch_bounds__(256) void k5_gemm(const float* __restrict__ W2,
                                               const float* __restrict__ a_src2,
                                               const float* __restrict__ a_dst2) {
    __shared__ float Ws[64 * 128];
    __shared__ float xs[NPB2 * 64];
    __shared__ float sals[2][16][4];
    __shared__ float sald[2][16][4];
    int t  = threadIdx.x;
    int nb = blockIdx.x * NPB2;
    {
        const float4* W4 = (const float4*)W2;
        float4* Wd = (float4*)Ws;
        for (int i = t; i < 64 * 128 / 4; i += 256) Wd[i] = W4[i];
        const float4* x4 = (const float4*)(d_out1 + nb * 64);
        float4* xd = (float4*)xs;
        for (int i = t; i < NPB2 * 64 / 4; i += 256) xd[i] = x4[i];
    }
    __syncthreads();
    int o   = t & 127;
    int nl0 = t >> 7;
    int w4  = (t >> 5) & 3;
    float acc[16];
#pragma unroll
    for (int r = 0; r < 16; r++) acc[r] = 0.f;
    const float4* xs4 = (const float4*)xs;
#pragma unroll 2
    for (int k4 = 0; k4 < 16; k4++) {
        float w0 = Ws[(k4 * 4 + 0) * 128 + o];
        float w1 = Ws[(k4 * 4 + 1) * 128 + o];
        float w2 = Ws[(k4 * 4 + 2) * 128 + o];
        float w3 = Ws[(k4 * 4 + 3) * 128 + o];
#pragma unroll
        for (int r = 0; r < 16; r++) {
            float4 xv = xs4[(nl0 + r * 2) * 16 + k4];
            acc[r] += xv.x * w0 + xv.y * w1 + xv.z * w2 + xv.w * w3;
        }
    }
#pragma unroll
    for (int r = 0; r < 16; r++)
        d_h2h[(nb + nl0 + r * 2) * 128 + o] = __float2half_rn(acc[r]);

    // fused logits: warp-reduce partial dot over this warp's 32 channels
    float a_s = a_src2[o];
    float a_d = a_dst2[o];
#pragma unroll
    for (int r = 0; r < 16; r++) {
        float cs = acc[r] * a_s;
        float cd = acc[r] * a_d;
#pragma unroll
        for (int off = 1; off < 32; off <<= 1) {
            cs += __shfl_xor_sync(0xffffffffu, cs, off);
            cd += __shfl_xor_sync(0xffffffffu, cd, off);
        }
        if ((t & 31) == 0) {
            sals[nl0][r][w4] = cs;
            sald[nl0][r][w4] = cd;
        }
    }
    __syncthreads();
    if (t < NPB2) {
        int nl = t & 1, r = t >> 1;
        d_als2[nb + t] = sals[nl][r][0] + sals[nl][r][1] + sals[nl][r][2] + sals[nl][r][3];
        d_ald2[nb + t] = sald[nl][r][0] + sald[nl][r][1] + sald[nl][r][2] + sald[nl][r][3];
    }
}

// ================= L2 aggregation: warp per dst node, single pass =================
__global__ __launch_bounds__(256) void l2_agg() {
    int gw   = (blockIdx.x * 256 + threadIdx.x) >> 5;
    int lane = threadIdx.x & 31;
    if (gw >= N_NODES) return;
    int dst = gw;
    int beg = d_rowptr[dst], end = d_rowptr[dst + 1];
    float ald = d_ald2[dst];

    float sum = 0.f;
    float4 acc = make_float4(0.f, 0.f, 0.f, 0.f);
#pragma unroll 2
    for (int i = beg; i < end; i++) {
        int src = d_esrc[i];
        float e = __expf(lrelu(d_als2[src] + ald));
        sum += e;
        __half2 hv[2];
        *(uint2*)hv = *(const uint2*)(d_h2h + src * 128 + lane * 4);
        float2 h0 = __half22float2(hv[0]);
        float2 h1 = __half22float2(hv[1]);
        acc.x += h0.x * e;
        acc.y += h0.y * e;
        acc.z += h1.x * e;
        acc.w += h1.y * e;
    }
    float inv = 1.f / (sum + 1e-16f);
    acc.x *= inv; acc.y *= inv; acc.z *= inv; acc.w *= inv;
    *(float4*)(d_out2 + dst * 128 + lane * 4) = acc;
}

// ================= K8: pool + FC + log_softmax =================
__global__ __launch_bounds__(128) void k8_pool(const int* __restrict__ batch,
                                               const float* __restrict__ b2,
                                               const float* __restrict__ fc_w,
                                               const float* __restrict__ fc_b,
                                               float* __restrict__ out) {
    int g = blockIdx.x;
    int t = threadIdx.x;
    int lo, hi;
    {
        int a = 0, b = N_NODES;
        while (a < b) { int m = (a + b) >> 1; if (batch[m] < g) a = m + 1; else b = m; }
        lo = a;
        a = lo; b = N_NODES;
        while (a < b) { int m = (a + b) >> 1; if (batch[m] < g + 1) a = m + 1; else b = m; }
        hi = a;
    }
    int cnt = hi - lo;
    float acc = 0.f;
    for (int n = lo; n < hi; n++) acc += d_out2[n * 128 + t];
    float inv = 1.f / (float)max(cnt, 1);
    __shared__ float sp[128];
    sp[t] = (acc + (float)cnt * b2[t]) * inv;
    __syncthreads();
    __shared__ float sl[N_CLASSES];
    if (t < N_CLASSES) {
        float v = fc_b[t];
        for (int k = 0; k < 128; k++) v += sp[k] * fc_w[k * N_CLASSES + t];
        sl[t] = v;
    }
    __syncthreads();
    __shared__ float s_m, s_lse;
    if (t == 0) {
        float m = sl[0];
        for (int c = 1; c < N_CLASSES; c++) m = fmaxf(m, sl[c]);
        float se = 0.f;
        for (int c = 0; c < N_CLASSES; c++) se += expf(sl[c] - m);
        s_m = m;
        s_lse = logf(se);
    }
    __syncthreads();
    if (t < N_CLASSES) out[g * N_CLASSES + t] = sl[t] - s_m - s_lse;
}

// ================= launch =================
extern "C" void kernel_launch(void* const* d_in, const int* in_sizes, int n_in,
                              void* d_out, int out_size) {
    const float* x      = (const float*)d_in[0];
    const int*   ei     = (const int*)d_in[1];
    const int*   batch  = (const int*)d_in[2];
    const float* W1     = (const float*)d_in[3];
    const float* a_src1 = (const float*)d_in[4];
    const float* a_dst1 = (const float*)d_in[5];
    const float* b1     = (const float*)d_in[6];
    const float* W2     = (const float*)d_in[7];
    const float* a_src2 = (const float*)d_in[8];
    const float* a_dst2 = (const float*)d_in[9];
    const float* b2     = (const float*)d_in[10];
    const float* fc_w   = (const float*)d_in[11];
    const float* fc_b   = (const float*)d_in[12];
    float* out = (float*)d_out;

    const int EB = (E_TOT + 255) / 256;
    const int WB = (N_NODES * 32 + 255) / 256;

    // CSR build
    k_zero_deg<<<NB_SCAN, SCAN_B>>>();
    k_hist<<<EB, 256>>>(ei);
    k_scan1<<<NB_SCAN, SCAN_B>>>();
    k_scan2<<<1, 256>>>();
    k_scan3<<<NB_SCAN, SCAN_B>>>();
    k_scatter<<<EB, 256>>>(ei);

    // layer 1
    k1_gemm<<<N_NODES / NPB1, 256>>>(x, W1, a_src1, a_dst1);
    l1_agg<<<WB, 256>>>(b1);

    // layer 2
    k5_gemm<<<N_NODES / NPB2, 256>>>(W2, a_src2, a_dst2);
    l2_agg<<<WB, 256>>>();

    // readout
    k8_pool<<<N_GRAPHS, 128>>>(batch, b2, fc_w, fc_b, out);
}

// round 8
// speedup vs baseline: 1.6744x; 1.0642x over previous
#include <cuda_runtime.h>
#include <cuda_fp16.h>

// Problem constants
#define N_NODES   100000
#define N_EDGES   1600000
#define E_TOT     (N_EDGES + N_NODES)   // with self-loops
#define N_FEAT    128
#define N_CLASSES 10
#define N_GRAPHS  256

#define SCAN_B    512
#define NB_SCAN   ((N_NODES + SCAN_B - 1) / SCAN_B)   // 196

// ---------------- device scratch ----------------
__device__ __align__(16) __half d_h1h[N_NODES * 64];    // layer1 features (gather-only)
__device__ __align__(16) float  d_als1[N_NODES * 8];
__device__ __align__(16) float  d_ald1[N_NODES * 8];
__device__ __align__(16) float  d_out1[N_NODES * 64];
__device__ __align__(16) __half d_h2h[N_NODES * 128];   // layer2 features (gather-only)
__device__ __align__(16) float  d_als2[N_NODES];
__device__ __align__(16) float  d_ald2[N_NODES];
__device__ __align__(16) float  d_out2[N_NODES * 128];

// CSR scratch
__device__ int d_deg   [N_NODES];
__device__ int d_incl  [N_NODES];
__device__ int d_bsum  [256];
__device__ int d_bofs  [256];
__device__ int d_rowptr[N_NODES + 1];
__device__ int d_wofs  [N_NODES];
__device__ int d_esrc  [E_TOT];

__device__ __forceinline__ float lrelu(float v) { return v > 0.f ? v : 0.2f * v; }

// ================= CSR build =================
__global__ void k_zero_deg() {
    int i = blockIdx.x * SCAN_B + threadIdx.x;
    if (i < N_NODES) d_deg[i] = 0;
}

__global__ void k_hist(const int* __restrict__ ei) {
    int e = blockIdx.x * 256 + threadIdx.x;
    if (e >= E_TOT) return;
    int dst = (e < N_EDGES) ? ei[N_EDGES + e] : (e - N_EDGES);
    atomicAdd(&d_deg[dst], 1);
}

__global__ __launch_bounds__(SCAN_B) void k_scan1() {
    __shared__ int s[SCAN_B];
    int i = blockIdx.x * SCAN_B + threadIdx.x;
    int v = (i < N_NODES) ? d_deg[i] : 0;
    s[threadIdx.x] = v;
    __syncthreads();
#pragma unroll
    for (int off = 1; off < SCAN_B; off <<= 1) {
        int t = (threadIdx.x >= off) ? s[threadIdx.x - off] : 0;
        __syncthreads();
        s[threadIdx.x] += t;
        __syncthreads();
    }
    if (i < N_NODES) d_incl[i] = s[threadIdx.x];
    if (threadIdx.x == SCAN_B - 1) d_bsum[blockIdx.x] = s[SCAN_B - 1];
}

__global__ __launch_bounds__(256) void k_scan2() {
    __shared__ int s[256];
    int t = threadIdx.x;
    int v = (t < NB_SCAN) ? d_bsum[t] : 0;
    s[t] = v;
    __syncthreads();
#pragma unroll
    for (int off = 1; off < 256; off <<= 1) {
        int u = (t >= off) ? s[t - off] : 0;
        __syncthreads();
        s[t] += u;
        __syncthreads();
    }
    if (t < NB_SCAN) d_bofs[t] = s[t] - v;   // exclusive
}

__global__ __launch_bounds__(SCAN_B) void k_scan3() {
    int i = blockIdx.x * SCAN_B + threadIdx.x;
    if (i < N_NODES) {
        int v = d_incl[i] + d_bofs[blockIdx.x];
        d_rowptr[i + 1] = v;
        if (i + 1 < N_NODES) d_wofs[i + 1] = v;
    }
    if (i == 0) { d_rowptr[0] = 0; d_wofs[0] = 0; }
}

__global__ void k_scatter(const int* __restrict__ ei) {
    int e = blockIdx.x * 256 + threadIdx.x;
    if (e >= E_TOT) return;
    int src, dst;
    if (e < N_EDGES) { src = ei[e]; dst = ei[N_EDGES + e]; }
    else             { src = dst = e - N_EDGES; }
    int pos = atomicAdd(&d_wofs[dst], 1);
    d_esrc[pos] = src;
}

// ================= K1: h1 = x @ W1 (100000x128 @ 128x64), register-tiled =================
// block tile: 64 rows x 64 cols, 256 threads, thread tile 4x4, 2 k-panels of 64
#define RPB1 64
__global__ __launch_bounds__(256) void k1_gemm(const float* __restrict__ x,
                                               const float* __restrict__ W1,
                                               const float* __restrict__ a_src1,
                                               const float* __restrict__ a_dst1) {
    __shared__ float xs[RPB1][64];   // [row][k-in-panel]  16KB
    __shared__ float Ws[64][64];     // [k-in-panel][col]  16KB
    int t  = threadIdx.x;
    int nb = blockIdx.x * RPB1;
    int tr = t >> 4;      // 0..15 row group
    int tc = t & 15;      // 0..15 col group
    float acc[4][4];
#pragma unroll
    for (int r = 0; r < 4; r++)
#pragma unroll
        for (int c = 0; c < 4; c++) acc[r][c] = 0.f;

    for (int p = 0; p < 2; p++) {
        __syncthreads();
        // load panels: x rows [nb..nb+63], k in [64p, 64p+64); W same k-range
        {
            // 256 threads load 64 rows x 16 float4 each
            int nl = t >> 2;          // 0..63 row
            int j0 = (t & 3) * 4;     // 4 float4 per thread
            int n = nb + nl;
            float4* xd = (float4*)&xs[nl][0];
            if (n < N_NODES) {
                const float4* xg = (const float4*)(x + n * 128 + p * 64);
#pragma unroll
                for (int j = 0; j < 4; j++) xd[j0 + j] = xg[j0 + j];
            } else {
                float4 z = make_float4(0.f, 0.f, 0.f, 0.f);
#pragma unroll
                for (int j = 0; j < 4; j++) xd[j0 + j] = z;
            }
            // W panel: 64 k x 64 cols = 1024 float4
            const float4* Wg = (const float4*)(W1 + (p * 64) * 64);
            float4* Wd = (float4*)&Ws[0][0];
            for (int i = t; i < 64 * 64 / 4; i += 256) Wd[i] = Wg[i];
        }
        __syncthreads();
#pragma unroll 2
        for (int kk = 0; kk < 64; kk++) {
            float4 wv = *(const float4*)&Ws[kk][tc * 4];
            float x0 = xs[tr * 4 + 0][kk];
            float x1 = xs[tr * 4 + 1][kk];
            float x2 = xs[tr * 4 + 2][kk];
            float x3 = xs[tr * 4 + 3][kk];
            acc[0][0] += x0 * wv.x; acc[0][1] += x0 * wv.y; acc[0][2] += x0 * wv.z; acc[0][3] += x0 * wv.w;
            acc[1][0] += x1 * wv.x; acc[1][1] += x1 * wv.y; acc[1][2] += x1 * wv.z; acc[1][3] += x1 * wv.w;
            acc[2][0] += x2 * wv.x; acc[2][1] += x2 * wv.y; acc[2][2] += x2 * wv.z; acc[2][3] += x2 * wv.w;
            acc[3][0] += x3 * wv.x; acc[3][1] += x3 * wv.y; acc[3][2] += x3 * wv.z; acc[3][3] += x3 * wv.w;
        }
    }

    // store fp16 h1 + fused logits
    float a_s[4], a_d[4];
#pragma unroll
    for (int c = 0; c < 4; c++) {
        a_s[c] = a_src1[tc * 4 + c];
        a_d[c] = a_dst1[tc * 4 + c];
    }
#pragma unroll
    for (int r = 0; r < 4; r++) {
        int n = nb + tr * 4 + r;
        bool ok = (n < N_NODES);
        if (ok) {
            __half2 p0 = __floats2half2_rn(acc[r][0], acc[r][1]);
            __half2 p1 = __floats2half2_rn(acc[r][2], acc[r][3]);
            uint2 u;
            u.x = *(unsigned*)&p0;
            u.y = *(unsigned*)&p1;
            *(uint2*)(d_h1h + n * 64 + tc * 4) = u;
        }
        float cs = acc[r][0] * a_s[0] + acc[r][1] * a_s[1] + acc[r][2] * a_s[2] + acc[r][3] * a_s[3];
        float cd = acc[r][0] * a_d[0] + acc[r][1] * a_d[1] + acc[r][2] * a_d[2] + acc[r][3] * a_d[3];
        cs += __shfl_xor_sync(0xffffffffu, cs, 1);
        cd += __shfl_xor_sync(0xffffffffu, cd, 1);
        if (((tc & 1) == 0) && ok) {
            int h = tc >> 1;   // 0..7
            d_als1[n * 8 + h] = cs;
            d_ald1[n * 8 + h] = cd;
        }
    }
}

// ================= L1 aggregation: warp per dst node, single pass =================
__global__ __launch_bounds__(256) void l1_agg(const float* __restrict__ b1) {
    int gw   = (blockIdx.x * 256 + threadIdx.x) >> 5;
    int lane = threadIdx.x & 31;
    if (gw >= N_NODES) return;
    int dst = gw;
    int beg = d_rowptr[dst], end = d_rowptr[dst + 1];
    int h8 = lane & 7;
    int myhead = lane >> 2;
    float ald_h = d_ald1[dst * 8 + h8];

    float sum = 0.f;
    float acc0 = 0.f, acc1 = 0.f;
#pragma unroll 2
    for (int i = beg; i < end; i++) {
        int src = d_esrc[i];
        float e_h = __expf(lrelu(d_als1[src * 8 + h8] + ald_h));
        sum += e_h;
        float alpha = __shfl_sync(0xffffffffu, e_h, myhead);
        __half2 hv = *(const __half2*)(d_h1h + src * 64 + lane * 2);
        float2 hf = __half22float2(hv);
        acc0 += hf.x * alpha;
        acc1 += hf.y * alpha;
    }
    float inv = 1.f / (__shfl_sync(0xffffffffu, sum, myhead) + 1e-16f);
    float r0 = acc0 * inv + b1[lane * 2];
    float r1 = acc1 * inv + b1[lane * 2 + 1];
    r0 = r0 > 0.f ? r0 : 0.f;
    r1 = r1 > 0.f ? r1 : 0.f;
    *(float2*)(d_out1 + dst * 64 + lane * 2) = make_float2(r0, r1);
}

// ================= K5: h2 = out1 @ W2 (100000x64 @ 64x128), register-tiled =================
// block tile: 64 rows x 128 cols, 256 threads, thread tile 4x8, 2 k-panels of 32
#define RPB2 64
__global__ __launch_bounds__(256) void k5_gemm(const float* __restrict__ W2,
                                               const float* __restrict__ a_src2,
                                               const float* __restrict__ a_dst2) {
    __shared__ float xs[RPB2][32];   // [row][k-in-panel]  8KB
    __shared__ float Ws[32][128];    // [k-in-panel][col]  16KB
    int t  = threadIdx.x;
    int nb = blockIdx.x * RPB2;
    int tr = t >> 4;     // 0..15 row group (4 rows)
    int tc = t & 15;     // 0..15 col group (8 cols)
    float acc[4][8];
#pragma unroll
    for (int r = 0; r < 4; r++)
#pragma unroll
        for (int c = 0; c < 8; c++) acc[r][c] = 0.f;

    for (int p = 0; p < 2; p++) {
        __syncthreads();
        {
            // x panel: 64 rows x 8 float4
            int nl = t >> 2;          // 0..63
            int j  = t & 3;           // 2 float4 per thread
            int n = nb + nl;
            float4* xd = (float4*)&xs[nl][0];
            if (n < N_NODES) {
                const float4* xg = (const float4*)(d_out1 + n * 64 + p * 32);
                xd[j] = xg[j];
                xd[j + 4] = xg[j + 4];
            } else {
                float4 z = make_float4(0.f, 0.f, 0.f, 0.f);
                xd[j] = z;
                xd[j + 4] = z;
            }
            // W panel: 32 k x 128 cols = 1024 float4
            const float4* Wg = (const float4*)(W2 + (p * 32) * 128);
            float4* Wd = (float4*)&Ws[0][0];
            for (int i = t; i < 32 * 128 / 4; i += 256) Wd[i] = Wg[i];
        }
        __syncthreads();
#pragma unroll 2
        for (int kk = 0; kk < 32; kk++) {
            float4 wv0 = *(const float4*)&Ws[kk][tc * 8];
            float4 wv1 = *(const float4*)&Ws[kk][tc * 8 + 4];
            float x0 = xs[tr * 4 + 0][kk];
            float x1 = xs[tr * 4 + 1][kk];
            float x2 = xs[tr * 4 + 2][kk];
            float x3 = xs[tr * 4 + 3][kk];
#define K5STEP(r, xv) \
            acc[r][0] += xv * wv0.x; acc[r][1] += xv * wv0.y; \
            acc[r][2] += xv * wv0.z; acc[r][3] += xv * wv0.w; \
            acc[r][4] += xv * wv1.x; acc[r][5] += xv * wv1.y; \
            acc[r][6] += xv * wv1.z; acc[r][7] += xv * wv1.w;
            K5STEP(0, x0) K5STEP(1, x1) K5STEP(2, x2) K5STEP(3, x3)
#undef K5STEP
        }
    }

    // store fp16 h2 + fused logits (1 head over 128 cols)
    float a_s[8], a_d[8];
#pragma unroll
    for (int c = 0; c < 8; c++) {
        a_s[c] = a_src2[tc * 8 + c];
        a_d[c] = a_dst2[tc * 8 + c];
    }
#pragma unroll
    for (int r = 0; r < 4; r++) {
        int n = nb + tr * 4 + r;
        bool ok = (n < N_NODES);
        if (ok) {
            __half2 p0 = __floats2half2_rn(acc[r][0], acc[r][1]);
            __half2 p1 = __floats2half2_rn(acc[r][2], acc[r][3]);
            __half2 p2 = __floats2half2_rn(acc[r][4], acc[r][5]);
            __half2 p3 = __floats2half2_rn(acc[r][6], acc[r][7]);
            uint4 u;
            u.x = *(unsigned*)&p0;
            u.y = *(unsigned*)&p1;
            u.z = *(unsigned*)&p2;
            u.w = *(unsigned*)&p3;
            *(uint4*)(d_h2h + n * 128 + tc * 8) = u;
        }
        float cs = 0.f, cd = 0.f;
#pragma unroll
        for (int c = 0; c < 8; c++) {
            cs += acc[r][c] * a_s[c];
            cd += acc[r][c] * a_d[c];
        }
#pragma unroll
        for (int off = 1; off < 16; off <<= 1) {
            cs += __shfl_xor_sync(0xffffffffu, cs, off);
            cd += __shfl_xor_sync(0xffffffffu, cd, off);
        }
        if (tc == 0 && ok) {
            d_als2[n] = cs;
            d_ald2[n] = cd;
        }
    }
}

// ================= L2 aggregation: warp per dst node, single pass =================
__global__ __launch_bounds__(256) void l2_agg() {
    int gw   = (blockIdx.x * 256 + threadIdx.x) >> 5;
    int lane = threadIdx.x & 31;
    if (gw >= N_NODES) return;
    int dst = gw;
    int beg = d_rowptr[dst], end = d_rowptr[dst + 1];
    float ald = d_ald2[dst];

    float sum = 0.f;
    float4 acc = make_float4(0.f, 0.f, 0.f, 0.f);
#pragma unroll 2
    for (int i = beg; i < end; i++) {
        int src = d_esrc[i];
        float e = __expf(lrelu(d_als2[src] + ald));
        sum += e;
        __half2 hv[2];
        *(uint2*)hv = *(const uint2*)(d_h2h + src * 128 + lane * 4);
        float2 h0 = __half22float2(hv[0]);
        float2 h1 = __half22float2(hv[1]);
        acc.x += h0.x * e;
        acc.y += h0.y * e;
        acc.z += h1.x * e;
        acc.w += h1.y * e;
    }
    float inv = 1.f / (sum + 1e-16f);
    acc.x *= inv; acc.y *= inv; acc.z *= inv; acc.w *= inv;
    *(float4*)(d_out2 + dst * 128 + lane * 4) = acc;
}

// ================= K8: pool + FC + log_softmax =================
__global__ __launch_bounds__(128) void k8_pool(const int* __restrict__ batch,
                                               const float* __restrict__ b2,
                                               const float* __restrict__ fc_w,
                                               const float* __restrict__ fc_b,
                                               float* __restrict__ out) {
    int g = blockIdx.x;
    int t = threadIdx.x;
    int lo, hi;
    {
        int a = 0, b = N_NODES;
        while (a < b) { int m = (a + b) >> 1; if (batch[m] < g) a = m + 1; else b = m; }
        lo = a;
        a = lo; b = N_NODES;
        while (a < b) { int m = (a + b) >> 1; if (batch[m] < g + 1) a = m + 1; else b = m; }
        hi = a;
    }
    int cnt = hi - lo;
    float acc = 0.f;
    for (int n = lo; n < hi; n++) acc += d_out2[n * 128 + t];
    float inv = 1.f / (float)max(cnt, 1);
    __shared__ float sp[128];
    sp[t] = (acc + (float)cnt * b2[t]) * inv;
    __syncthreads();
    __shared__ float sl[N_CLASSES];
    if (t < N_CLASSES) {
        float v = fc_b[t];
        for (int k = 0; k < 128; k++) v += sp[k] * fc_w[k * N_CLASSES + t];
        sl[t] = v;
    }
    __syncthreads();
    __shared__ float s_m, s_lse;
    if (t == 0) {
        float m = sl[0];
        for (int c = 1; c < N_CLASSES; c++) m = fmaxf(m, sl[c]);
        float se = 0.f;
        for (int c = 0; c < N_CLASSES; c++) se += expf(sl[c] - m);
        s_m = m;
        s_lse = logf(se);
    }
    __syncthreads();
    if (t < N_CLASSES) out[g * N_CLASSES + t] = sl[t] - s_m - s_lse;
}

// ================= launch =================
extern "C" void kernel_launch(void* const* d_in, const int* in_sizes, int n_in,
                              void* d_out, int out_size) {
    const float* x      = (const float*)d_in[0];
    const int*   ei     = (const int*)d_in[1];
    const int*   batch  = (const int*)d_in[2];
    const float* W1     = (const float*)d_in[3];
    const float* a_src1 = (const float*)d_in[4];
    const float* a_dst1 = (const float*)d_in[5];
    const float* b1     = (const float*)d_in[6];
    const float* W2     = (const float*)d_in[7];
    const float* a_src2 = (const float*)d_in[8];
    const float* a_dst2 = (const float*)d_in[9];
    const float* b2     = (const float*)d_in[10];
    const float* fc_w   = (const float*)d_in[11];
    const float* fc_b   = (const float*)d_in[12];
    float* out = (float*)d_out;

    const int EB = (E_TOT + 255) / 256;
    const int WB = (N_NODES * 32 + 255) / 256;
    const int GB = (N_NODES + RPB1 - 1) / RPB1;   // 1563

    // CSR build
    k_zero_deg<<<NB_SCAN, SCAN_B>>>();
    k_hist<<<EB, 256>>>(ei);
    k_scan1<<<NB_SCAN, SCAN_B>>>();
    k_scan2<<<1, 256>>>();
    k_scan3<<<NB_SCAN, SCAN_B>>>();
    k_scatter<<<EB, 256>>>(ei);

    // layer 1
    k1_gemm<<<GB, 256>>>(x, W1, a_src1, a_dst1);
    l1_agg<<<WB, 256>>>(b1);

    // layer 2
    k5_gemm<<<GB, 256>>>(W2, a_src2, a_dst2);
    l2_agg<<<WB, 256>>>();

    // readout
    k8_pool<<<N_GRAPHS, 128>>>(batch, b2, fc_w, fc_b, out);
}